// round 15
// baseline (speedup 1.0000x reference)
#include <cuda_runtime.h>
#include <cuda_fp16.h>
#include <cstdint>

#define NQ 8
#define BINS 1024
#define DIM 256
#define BB 8
#define TT 8192
#define NTOK (BB*TT)            // 65536
#define MT 256
#define NBLK (NTOK/MT)          // 256
#define QOFF 16777216
#define COFF (QOFF + NQ*NTOK)

#define ASTR_H 264
#define ASTR_B 528
#define A_BYTES (MT*ASTR_B)     // 135168
#define CHUNK_B 16384
#define NCHUNKS 256

#define SO_CBSQ 0
#define SO_SIDX 4096
#define SO_SSQ  5120
#define SO_MBAR 5152
#define SO_RSQ  5216
#define SO_FCNT 6240
#define SO_FTOK 6256
#define SO_FESC 7280
#define SO_CAND 8304            // 256 x 8 ints
#define SO_AHI  16640
#define SO_B    (SO_AHI + A_BYTES)      // 151808
#define SMEM_BYTES (SO_B + 4*CHUNK_B)   // 217344

__device__ __align__(128) unsigned char g_bimg[(size_t)NCHUNKS*CHUNK_B]; // 4MB
__device__ float g_res[(size_t)NTOK*DIM];   // exact fp32 residual
__device__ float g_cbsq[NQ*BINS];
__device__ int   g_cmaxbits[NQ];
__device__ float g_ssq[NQ*NBLK];

static __device__ __forceinline__ uint32_t smem_u32(const void* p){
    uint32_t a;
    asm("{ .reg .u64 t; cvta.to.shared.u64 t, %1; cvt.u32.u64 %0, t; }":"=r"(a):"l"(p));
    return a;
}
#define MBAR_INIT(a,c) asm volatile("mbarrier.init.shared.b64 [%0], %1;"::"r"(a),"r"(c):"memory")
#define MBAR_ARRIVE(a) asm volatile("mbarrier.arrive.shared.b64 _, [%0];"::"r"(a):"memory")
#define MBAR_EXPECT_TX(a,b) asm volatile("mbarrier.arrive.expect_tx.shared.b64 _, [%0], %1;"::"r"(a),"r"(b):"memory")
static __device__ __forceinline__ void mbar_wait(uint32_t a, uint32_t ph){
    asm volatile("{\n\t.reg .pred P;\nW%=: mbarrier.try_wait.parity.acquire.cta.shared::cta.b64 P, [%0], %1, 0x989680;\n\t@!P bra W%=;\n\t}"
        ::"r"(a),"r"(ph):"memory");
}
static __device__ __forceinline__ void bulkcp(uint32_t dst, const void* src,
                                              uint32_t bytes, uint32_t mb){
    asm volatile("cp.async.bulk.shared::cta.global.mbarrier::complete_tx::bytes [%0], [%1], %2, [%3];"
        ::"r"(dst),"l"(src),"r"(bytes),"r"(mb):"memory");
}
static __device__ __forceinline__ void ldsm4(uint32_t* r, uint32_t a){
    asm volatile("ldmatrix.sync.aligned.m8n8.x4.shared.b16 {%0,%1,%2,%3}, [%4];"
        :"=r"(r[0]),"=r"(r[1]),"=r"(r[2]),"=r"(r[3]):"r"(a));
}
static __device__ __forceinline__ void mma16816(float* c, const uint32_t* a,
                                                uint32_t b0, uint32_t b1){
    asm volatile("mma.sync.aligned.m16n8k16.row.col.f32.f16.f16.f32 "
        "{%0,%1,%2,%3}, {%4,%5,%6,%7}, {%8,%9}, {%0,%1,%2,%3};"
        : "+f"(c[0]),"+f"(c[1]),"+f"(c[2]),"+f"(c[3])
        : "r"(a[0]),"r"(a[1]),"r"(a[2]),"r"(a[3]),"r"(b0),"r"(b1));
}
// pack bin index into 10 mantissa LSBs of the distance (branchless argmin keys)
static __device__ __forceinline__ float packkey(float d, uint32_t n){
    return __uint_as_float((__float_as_uint(d) & 0xFFFFFC00u) | n);
}
static __device__ __forceinline__ void upd2(float& b1, float& b2, float k){
    float mx = fmaxf(b1, k);
    b1 = fminf(b1, k);
    b2 = fminf(b2, mx);
}

__global__ void rvq_prep_kernel(const float* __restrict__ cbs){
    int id = blockIdx.x*blockDim.x + threadIdx.x;
    if (id >= NQ*BINS*DIM) return;
    int d = id & 255, j = (id>>8) & 1023, q = id>>18;
    __half hi = __float2half_rn(cbs[id]);
    int jc = j>>5, jr = j&31;
    uint32_t unit = (uint32_t)(d>>3);
    uint32_t off = (uint32_t)jr*512u + ((unit ^ (uint32_t)(jr&7))<<4) + (uint32_t)(d&7)*2u;
    *(__half*)(g_bimg + (size_t)(q*32+jc)*CHUNK_B + off) = hi;
}

__global__ void rvq_cbsq_kernel(const float* __restrict__ cbs){
    int id = blockIdx.x*blockDim.x + threadIdx.x;
    if (id >= NQ*BINS) return;
    const float* c = cbs + (size_t)id*DIM;
    float s0=0,s1=0,s2=0,s3=0;
    #pragma unroll 8
    for (int d=0; d<DIM; d+=4){
        float4 v = *(const float4*)(c+d);
        s0=fmaf(v.x,v.x,s0); s1=fmaf(v.y,v.y,s1); s2=fmaf(v.z,v.z,s2); s3=fmaf(v.w,v.w,s3);
    }
    float n2 = (s0+s1)+(s2+s3);
    g_cbsq[id] = n2;
    atomicMax(&g_cmaxbits[id>>10], __float_as_int(n2));
}

__global__ __launch_bounds__(256,1)
void rvq_main_kernel(const float* __restrict__ x, const float* __restrict__ cbs,
                     float* __restrict__ out){
    extern __shared__ char smc[];
    const uint32_t sb = smem_u32(smc);
    const int tid = threadIdx.x, l = tid&31, w = tid>>5, bid = blockIdx.x;
    const int b = bid>>5, t0 = (bid&31)<<8;
    const float* xblk = x + ((size_t)b*DIM)*TT + t0;
    float* gres = g_res + ((size_t)bid)*MT*DIM;
    float* cbsq_s = (float*)(smc+SO_CBSQ);
    int*   sidx   = (int*)(smc+SO_SIDX);
    float* ssqs   = (float*)(smc+SO_SSQ);
    float* rsq    = (float*)(smc+SO_RSQ);
    int*   fcnt   = (int*)(smc+SO_FCNT);
    int*   ftok   = (int*)(smc+SO_FTOK);
    int*   fesc   = (int*)(smc+SO_FESC);
    int*   cand   = (int*)(smc+SO_CAND);
    __half* pH = (__half*)(smc+SO_AHI);
    #define FULLB(i)  (sb+SO_MBAR + (uint32_t)(i)*8u)
    #define EMPTYB(i) (sb+SO_MBAR + 32u + (uint32_t)(i)*8u)

    if (tid==0){
        #pragma unroll
        for (int i=0;i<4;++i){ MBAR_INIT(FULLB(i),1); MBAR_INIT(EMPTYB(i),8); }
    }

    for (int i=tid; i<DIM*MT; i+=256){
        int d = i>>8, m = i&255;
        float v = xblk[(size_t)d*TT+m];
        pH[m*ASTR_H + d] = __float2half_rn(v);
        gres[(size_t)m*DIM + d] = v;
    }
    __syncthreads();
    if (tid < MT){
        float s = 0.f;
        const float* rr = gres + (size_t)tid*DIM;
        for (int d=0; d<DIM; d+=4){
            float4 v = *(const float4*)(rr+d);
            s = fmaf(v.x,v.x,fmaf(v.y,v.y,fmaf(v.z,v.z,fmaf(v.w,v.w,s))));
        }
        rsq[tid] = s;
    }
    __syncthreads();

    const uint32_t aW0 = sb + SO_AHI + (w*32 + (l&15))*ASTR_B + (l>>4)*16;
    const uint32_t aW1 = aW0 + 16*ASTR_B;
    const int nr  = (l&7) | ((l&16)>>1);
    const int suu = (l>>3)&1;
    const uint32_t xorv = (uint32_t)(nr&7);
    const uint32_t bRow = sb + SO_B + (uint32_t)nr*512u;
    const int grpLead = l & ~3;

    int pf[4] = {0,0,0,0};
    int pe[4] = {1,1,1,1};

    if (tid==0){
        #pragma unroll
        for (int p=0; p<3; ++p){
            mbar_wait(EMPTYB(p), pe[p]); pe[p]^=1;
            MBAR_EXPECT_TX(FULLB(p), CHUNK_B);
            bulkcp(sb+SO_B+(uint32_t)p*CHUNK_B, g_bimg + (size_t)p*CHUNK_B, CHUNK_B, FULLB(p));
        }
    }

    for (int q=0; q<NQ; ++q){
        const float* cbq = cbs + (size_t)q*BINS*DIM;
        for (int i=tid; i<BINS; i+=256) cbsq_s[i] = g_cbsq[q*BINS+i];
        if (tid==0) fcnt[0] = 0;
        const float CE = 1.96e-3f * sqrtf(__int_as_float(g_cmaxbits[q]));
        __syncthreads();

        float k1[4] = {3.4e38f,3.4e38f,3.4e38f,3.4e38f};
        float k2[4] = {3.4e38f,3.4e38f,3.4e38f,3.4e38f};

        for (int c=0; c<32; ++c){
            const int G = q*32 + c;
            if (tid==0 && G+3 < NCHUNKS){
                const int s3 = (G+3)&3;
                mbar_wait(EMPTYB(s3), pe[s3]); pe[s3]^=1;
                MBAR_EXPECT_TX(FULLB(s3), CHUNK_B);
                bulkcp(sb+SO_B+(uint32_t)s3*CHUNK_B,
                       g_bimg + (size_t)(G+3)*CHUNK_B, CHUNK_B, FULLB(s3));
            }
            const int s = G&3;
            mbar_wait(FULLB(s), pf[s]); pf[s]^=1;

            float acc[2][4][4];
            #pragma unroll
            for (int ti=0;ti<2;++ti)
                #pragma unroll
                for (int t=0;t<4;++t)
                    #pragma unroll
                    for (int i=0;i<4;++i) acc[ti][t][i]=0.f;

            const uint32_t bbase = bRow + (uint32_t)s*CHUNK_B;

            uint32_t a0[4], a1[4], bg0[4], bg1[4];
            {
                ldsm4(a0, aW0);
                ldsm4(a1, aW1);
                const uint32_t cb0 = ((((uint32_t)suu) ^ xorv) << 4);
                ldsm4(bg0, bbase + cb0);
                ldsm4(bg1, bbase + 8192u + cb0);
            }
            #pragma unroll
            for (int kt=0; kt<16; ++kt){
                uint32_t na0[4], na1[4], nb0[4], nb1[4];
                if (kt < 15){
                    ldsm4(na0, aW0 + (kt+1)*32);
                    ldsm4(na1, aW1 + (kt+1)*32);
                    const uint32_t cbn = ((((uint32_t)((kt+1)*2+suu)) ^ xorv) << 4);
                    ldsm4(nb0, bbase + cbn);
                    ldsm4(nb1, bbase + 8192u + cbn);
                }
                mma16816(acc[0][0], a0, bg0[0], bg0[1]);
                mma16816(acc[0][1], a0, bg0[2], bg0[3]);
                mma16816(acc[0][2], a0, bg1[0], bg1[1]);
                mma16816(acc[0][3], a0, bg1[2], bg1[3]);
                mma16816(acc[1][0], a1, bg0[0], bg0[1]);
                mma16816(acc[1][1], a1, bg0[2], bg0[3]);
                mma16816(acc[1][2], a1, bg1[0], bg1[1]);
                mma16816(acc[1][3], a1, bg1[2], bg1[3]);
                if (kt < 15){
                    #pragma unroll
                    for (int i=0;i<4;++i){
                        a0[i]=na0[i]; a1[i]=na1[i]; bg0[i]=nb0[i]; bg1[i]=nb1[i];
                    }
                }
            }
            if (l==0) MBAR_ARRIVE(EMPTYB(s));

            // branchless key-based top-2 epilogue
            #pragma unroll
            for (int ti=0;ti<2;++ti){
                #pragma unroll
                for (int t=0;t<4;++t){
                    uint32_t n = (uint32_t)(c*32 + t*8 + (l&3)*2);
                    float cq0 = cbsq_s[n], cq1 = cbsq_s[n+1];
                    float ky0 = packkey(fmaf(-2.f, acc[ti][t][0], cq0), n);
                    float ky1 = packkey(fmaf(-2.f, acc[ti][t][1], cq1), n+1);
                    float ky2 = packkey(fmaf(-2.f, acc[ti][t][2], cq0), n);
                    float ky3 = packkey(fmaf(-2.f, acc[ti][t][3], cq1), n+1);
                    upd2(k1[ti*2],   k2[ti*2],   ky0);
                    upd2(k1[ti*2],   k2[ti*2],   ky1);
                    upd2(k1[ti*2+1], k2[ti*2+1], ky2);
                    upd2(k1[ti*2+1], k2[ti*2+1], ky3);
                }
            }
        }

        #pragma unroll
        for (int slot=0; slot<4; ++slot){
            const float p1 = k1[slot], p2 = k2[slot];   // lane-local (candidates)
            float g1 = p1, g2 = p2;
            #pragma unroll
            for (int off=1; off<=2; off<<=1){
                float o1 = __shfl_xor_sync(0xFFFFFFFFu, g1, off);
                float o2 = __shfl_xor_sync(0xFFFFFFFFu, g2, off);
                float mx = fmaxf(g1, o1);
                g1 = fminf(g1, o1);
                g2 = fminf(fminf(g2, o2), mx);
            }
            int m = w*32 + (slot>>1)*16 + (l>>2) + (slot&1)*8;
            float E = CE * sqrtf(fmaxf(rsq[m], 0.f));
            float epsw = 2.1f*E + 0.03f + 5e-4f*(fabsf(g1)+1.f);  // + key-quantization slack
            float W = g1 + epsw;
            bool flag = (g2 <= W);
            int fi = -1;
            if (flag && (l&3)==0) fi = atomicAdd(fcnt, 1);
            fi = __shfl_sync(0xFFFFFFFFu, fi, grpLead);
            int escb = (p2 <= W) ? 1 : 0;     // lane 3rd-best unknown -> escalate
            escb |= __shfl_xor_sync(0xFFFFFFFFu, escb, 1);
            escb |= __shfl_xor_sync(0xFFFFFFFFu, escb, 2);
            if (flag){
                if ((l&3)==0){ ftok[fi] = m; fesc[fi] = escb; }
                cand[fi*8 + (l&3)*2 + 0] = (p1 <= W) ? (int)(__float_as_uint(p1)&1023u) : -1;
                cand[fi*8 + (l&3)*2 + 1] = (p2 <= W) ? (int)(__float_as_uint(p2)&1023u) : -1;
            } else if ((l&3)==0){
                int b1i = (int)(__float_as_uint(g1)&1023u);
                sidx[m] = b1i;
                out[QOFF + ((size_t)(q*BB+b))*TT + t0 + m] = (float)b1i;
                rsq[m] = fmaxf(rsq[m] + g1 + epsw, 0.f);
            }
        }
        __syncthreads();

        {
            const int nf = fcnt[0];
            for (int f = w; f < nf; f += 8){
                int m = ftok[f], esc = fesc[f];
                float rv[8];
                const float* rr = gres + (size_t)m*DIM + l*8;
                float4 r4a = *(const float4*)(rr), r4b = *(const float4*)(rr+4);
                rv[0]=r4a.x; rv[1]=r4a.y; rv[2]=r4a.z; rv[3]=r4a.w;
                rv[4]=r4b.x; rv[5]=r4b.y; rv[6]=r4b.z; rv[7]=r4b.w;
                float be = 3.4e38f; int bj = 0;
                if (!esc){
                    for (int k=0; k<8; ++k){
                        int j = cand[f*8+k];
                        if (j < 0) continue;
                        const float4* cr = (const float4*)(cbq + (size_t)j*DIM + l*8);
                        float4 ca = cr[0], cb2 = cr[1];
                        float s = rv[0]*ca.x + rv[1]*ca.y + rv[2]*ca.z + rv[3]*ca.w
                                + rv[4]*cb2.x + rv[5]*cb2.y + rv[6]*cb2.z + rv[7]*cb2.w;
                        #pragma unroll
                        for (int off2=16; off2>0; off2>>=1) s += __shfl_xor_sync(0xFFFFFFFFu, s, off2);
                        float e2 = cbsq_s[j] - 2.f*s;
                        if (e2 < be || (e2 == be && j < bj)){ be = e2; bj = j; }
                    }
                } else {
                    for (int j=0; j<BINS; ++j){
                        const float4* cr = (const float4*)(cbq + (size_t)j*DIM + l*8);
                        float4 ca = cr[0], cb2 = cr[1];
                        float s = rv[0]*ca.x + rv[1]*ca.y + rv[2]*ca.z + rv[3]*ca.w
                                + rv[4]*cb2.x + rv[5]*cb2.y + rv[6]*cb2.z + rv[7]*cb2.w;
                        #pragma unroll
                        for (int off2=16; off2>0; off2>>=1) s += __shfl_xor_sync(0xFFFFFFFFu, s, off2);
                        float e2 = cbsq_s[j] - 2.f*s;
                        if (e2 < be){ be = e2; bj = j; }
                    }
                }
                if (l==0){
                    sidx[m] = bj;
                    out[QOFF + ((size_t)(q*BB+b))*TT + t0 + m] = (float)bj;
                    rsq[m] = fmaxf(rsq[m] + be + 0.05f, 0.f);
                }
            }
        }
        __syncthreads();

        {
            float ssq = 0.f;
            #pragma unroll 4
            for (int m=0; m<MT; ++m){
                int ix = sidx[m];
                float cv = __ldg(cbq + (size_t)ix*DIM + tid);
                float r = gres[(size_t)m*DIM + tid];
                float rn = r - cv;
                gres[(size_t)m*DIM + tid] = rn;
                pH[m*ASTR_H + tid] = __float2half_rn(rn);
                ssq = fmaf(rn, rn, ssq);
            }
            #pragma unroll
            for (int o2=16;o2>0;o2>>=1) ssq += __shfl_xor_sync(0xFFFFFFFFu, ssq, o2);
            if (l==0) ssqs[w] = ssq;
            __syncthreads();
            if (tid==0){
                float sacc=0.f;
                #pragma unroll
                for (int ww=0; ww<8; ++ww) sacc += ssqs[ww];
                g_ssq[q*NBLK+bid] = sacc;
            }
            __syncthreads();
        }
    }

    for (int i=tid; i<DIM*MT; i+=256){
        int d = i>>8, m = i&255;
        out[((size_t)b*DIM+d)*TT + t0 + m] =
            xblk[(size_t)d*TT+m] - gres[(size_t)m*DIM + d];
    }
}

__global__ void rvq_finalize_kernel(const int* __restrict__ sr_raw, float* __restrict__ out){
    __shared__ float red[8];
    const int tid = threadIdx.x;
    float s = 0.f;
    #pragma unroll
    for (int i=0; i<NQ*NBLK/256; ++i) s += g_ssq[tid + i*256];
    #pragma unroll
    for (int o=16;o>0;o>>=1) s += __shfl_xor_sync(0xFFFFFFFFu, s, o);
    if ((tid&31)==0) red[tid>>5] = s;
    __syncthreads();
    if (tid==0){
        float tot=0.f;
        #pragma unroll
        for (int w=0; w<8; ++w) tot += red[w];
        int iv = sr_raw[0];
        float sr = (iv > 0 && iv < 100000000) ? (float)iv : __int_as_float(iv);
        out[COFF+0] = (float)NQ * 10.0f * (sr / 1000.0f);
        out[COFF+1] = tot * (0.25f / ((float)((size_t)NTOK*DIM))) / (float)NQ;
    }
}

extern "C" void kernel_launch(void* const* d_in, const int* in_sizes, int n_in,
                              void* d_out, int out_size){
    const float* x   = (const float*)d_in[0];
    const int*   sr  = (const int*)d_in[1];
    const float* cbs = (const float*)d_in[2];
    float* out = (float*)d_out;
    cudaFuncSetAttribute(rvq_main_kernel, cudaFuncAttributeMaxDynamicSharedMemorySize, SMEM_BYTES);
    rvq_prep_kernel<<<(NQ*BINS*DIM+255)/256, 256>>>(cbs);
    rvq_cbsq_kernel<<<(NQ*BINS+255)/256, 256>>>(cbs);
    rvq_main_kernel<<<NBLK, 256, SMEM_BYTES>>>(x, cbs, out);
    rvq_finalize_kernel<<<1, 256>>>(sr, out);
}

// round 16
// speedup vs baseline: 2.2945x; 2.2945x over previous
#include <cuda_runtime.h>
#include <cuda_fp16.h>
#include <cstdint>

#define NQ 8
#define BINS 1024
#define DIM 256
#define BB 8
#define TT 8192
#define NTOK (BB*TT)            // 65536
#define MT 256
#define NBLK (NTOK/MT)          // 256
#define QOFF 16777216
#define COFF (QOFF + NQ*NTOK)

#define ASTR_H 264
#define ASTR_B 528
#define A_BYTES (MT*ASTR_B)     // 135168
#define CHUNK_B 16384
#define NCHUNKS 256

#define SO_CBSQ 0
#define SO_SIDX 4096
#define SO_SSQ  5120
#define SO_MBAR 5152
#define SO_RSQ  5216
#define SO_FCNT 6240
#define SO_FTOK 6256
#define SO_FESC 7280
#define SO_CAND 8304            // 256 x 12 ints
#define SO_AHI  20608
#define SO_B    (SO_AHI + A_BYTES)      // 155776
#define SMEM_BYTES (SO_B + 4*CHUNK_B)   // 221312

__device__ __align__(128) unsigned char g_bimg[(size_t)NCHUNKS*CHUNK_B]; // 4MB
__device__ float g_res[(size_t)NTOK*DIM];   // exact fp32 residual
__device__ float g_cbsq[NQ*BINS];
__device__ int   g_cmaxbits[NQ];
__device__ float g_ssq[NQ*NBLK];

static __device__ __forceinline__ uint32_t smem_u32(const void* p){
    uint32_t a;
    asm("{ .reg .u64 t; cvta.to.shared.u64 t, %1; cvt.u32.u64 %0, t; }":"=r"(a):"l"(p));
    return a;
}
#define MBAR_INIT(a,c) asm volatile("mbarrier.init.shared.b64 [%0], %1;"::"r"(a),"r"(c):"memory")
#define MBAR_ARRIVE(a) asm volatile("mbarrier.arrive.shared.b64 _, [%0];"::"r"(a):"memory")
#define MBAR_EXPECT_TX(a,b) asm volatile("mbarrier.arrive.expect_tx.shared.b64 _, [%0], %1;"::"r"(a),"r"(b):"memory")
static __device__ __forceinline__ void mbar_wait(uint32_t a, uint32_t ph){
    asm volatile("{\n\t.reg .pred P;\nW%=: mbarrier.try_wait.parity.acquire.cta.shared::cta.b64 P, [%0], %1, 0x989680;\n\t@!P bra W%=;\n\t}"
        ::"r"(a),"r"(ph):"memory");
}
static __device__ __forceinline__ void bulkcp(uint32_t dst, const void* src,
                                              uint32_t bytes, uint32_t mb){
    asm volatile("cp.async.bulk.shared::cta.global.mbarrier::complete_tx::bytes [%0], [%1], %2, [%3];"
        ::"r"(dst),"l"(src),"r"(bytes),"r"(mb):"memory");
}
static __device__ __forceinline__ void ldsm4(uint32_t* r, uint32_t a){
    asm volatile("ldmatrix.sync.aligned.m8n8.x4.shared.b16 {%0,%1,%2,%3}, [%4];"
        :"=r"(r[0]),"=r"(r[1]),"=r"(r[2]),"=r"(r[3]):"r"(a));
}
static __device__ __forceinline__ void mma16816(float* c, const uint32_t* a,
                                                uint32_t b0, uint32_t b1){
    asm volatile("mma.sync.aligned.m16n8k16.row.col.f32.f16.f16.f32 "
        "{%0,%1,%2,%3}, {%4,%5,%6,%7}, {%8,%9}, {%0,%1,%2,%3};"
        : "+f"(c[0]),"+f"(c[1]),"+f"(c[2]),"+f"(c[3])
        : "r"(a[0]),"r"(a[1]),"r"(a[2]),"r"(a[3]),"r"(b0),"r"(b1));
}
#define INS4(vv, xx, nv, ni) do{ \
  if ((nv) < vv[3]) { \
    if ((nv) < vv[1]) { \
      vv[3]=vv[2]; xx[3]=xx[2]; vv[2]=vv[1]; xx[2]=xx[1]; \
      if ((nv) < vv[0]) { vv[1]=vv[0]; xx[1]=xx[0]; vv[0]=(nv); xx[0]=(ni); } \
      else { vv[1]=(nv); xx[1]=(ni); } \
    } else { \
      if ((nv) < vv[2]) { vv[3]=vv[2]; xx[3]=xx[2]; vv[2]=(nv); xx[2]=(ni); } \
      else { vv[3]=(nv); xx[3]=(ni); } \
    } \
  } }while(0)

__global__ void rvq_prep_kernel(const float* __restrict__ cbs){
    int id = blockIdx.x*blockDim.x + threadIdx.x;
    if (id >= NQ*BINS*DIM) return;
    int d = id & 255, j = (id>>8) & 1023, q = id>>18;
    __half hi = __float2half_rn(cbs[id]);
    int jc = j>>5, jr = j&31;
    uint32_t unit = (uint32_t)(d>>3);
    uint32_t off = (uint32_t)jr*512u + ((unit ^ (uint32_t)(jr&7))<<4) + (uint32_t)(d&7)*2u;
    *(__half*)(g_bimg + (size_t)(q*32+jc)*CHUNK_B + off) = hi;
}

__global__ void rvq_cbsq_kernel(const float* __restrict__ cbs){
    int id = blockIdx.x*blockDim.x + threadIdx.x;
    if (id >= NQ*BINS) return;
    const float* c = cbs + (size_t)id*DIM;
    float s0=0,s1=0,s2=0,s3=0;
    #pragma unroll 8
    for (int d=0; d<DIM; d+=4){
        float4 v = *(const float4*)(c+d);
        s0=fmaf(v.x,v.x,s0); s1=fmaf(v.y,v.y,s1); s2=fmaf(v.z,v.z,s2); s3=fmaf(v.w,v.w,s3);
    }
    float n2 = (s0+s1)+(s2+s3);
    g_cbsq[id] = n2;
    atomicMax(&g_cmaxbits[id>>10], __float_as_int(n2));
}

__global__ __launch_bounds__(256,1)
void rvq_main_kernel(const float* __restrict__ x, const float* __restrict__ cbs,
                     float* __restrict__ out){
    extern __shared__ char smc[];
    const uint32_t sb = smem_u32(smc);
    const int tid = threadIdx.x, l = tid&31, w = tid>>5, bid = blockIdx.x;
    const int b = bid>>5, t0 = (bid&31)<<8;
    const float* xblk = x + ((size_t)b*DIM)*TT + t0;
    float* gres = g_res + ((size_t)bid)*MT*DIM;
    float* cbsq_s = (float*)(smc+SO_CBSQ);
    int*   sidx   = (int*)(smc+SO_SIDX);
    float* ssqs   = (float*)(smc+SO_SSQ);
    float* rsq    = (float*)(smc+SO_RSQ);
    int*   fcnt   = (int*)(smc+SO_FCNT);
    int*   ftok   = (int*)(smc+SO_FTOK);
    int*   fesc   = (int*)(smc+SO_FESC);
    int*   cand   = (int*)(smc+SO_CAND);
    __half* pH = (__half*)(smc+SO_AHI);
    #define FULLB(i)  (sb+SO_MBAR + (uint32_t)(i)*8u)
    #define EMPTYB(i) (sb+SO_MBAR + 32u + (uint32_t)(i)*8u)

    if (tid==0){
        #pragma unroll
        for (int i=0;i<4;++i){ MBAR_INIT(FULLB(i),1); MBAR_INIT(EMPTYB(i),8); }
    }

    for (int i=tid; i<DIM*MT; i+=256){
        int d = i>>8, m = i&255;
        float v = xblk[(size_t)d*TT+m];
        pH[m*ASTR_H + d] = __float2half_rn(v);
        gres[(size_t)m*DIM + d] = v;
    }
    __syncthreads();
    if (tid < MT){
        float s = 0.f;
        const float* rr = gres + (size_t)tid*DIM;
        for (int d=0; d<DIM; d+=4){
            float4 v = *(const float4*)(rr+d);
            s = fmaf(v.x,v.x,fmaf(v.y,v.y,fmaf(v.z,v.z,fmaf(v.w,v.w,s))));
        }
        rsq[tid] = s;
    }
    __syncthreads();

    const uint32_t aW0 = sb + SO_AHI + (w*32 + (l&15))*ASTR_B + (l>>4)*16;
    const uint32_t aW1 = aW0 + 16*ASTR_B;
    const int nr  = (l&7) | ((l&16)>>1);
    const int suu = (l>>3)&1;
    const uint32_t xorv = (uint32_t)(nr&7);
    const uint32_t bRow = sb + SO_B + (uint32_t)nr*512u;
    const int grpLead = l & ~3;

    int pf[4] = {0,0,0,0};
    int pe[4] = {1,1,1,1};

    if (tid==0){
        #pragma unroll
        for (int p=0; p<3; ++p){
            mbar_wait(EMPTYB(p), pe[p]); pe[p]^=1;
            MBAR_EXPECT_TX(FULLB(p), CHUNK_B);
            bulkcp(sb+SO_B+(uint32_t)p*CHUNK_B, g_bimg + (size_t)p*CHUNK_B, CHUNK_B, FULLB(p));
        }
    }

    for (int q=0; q<NQ; ++q){
        const float* cbq = cbs + (size_t)q*BINS*DIM;
        for (int i=tid; i<BINS; i+=256) cbsq_s[i] = g_cbsq[q*BINS+i];
        if (tid==0) fcnt[0] = 0;
        const float CE = 1.96e-3f * sqrtf(__int_as_float(g_cmaxbits[q]));
        __syncthreads();

        // A fragments resident for the whole step (residual is constant per q)
        uint32_t af[16][8];
        #pragma unroll
        for (int kt=0; kt<16; ++kt){
            ldsm4(&af[kt][0], aW0 + kt*32);
            ldsm4(&af[kt][4], aW1 + kt*32);
        }

        float vv[4][4]; int xx[4][4];
        #pragma unroll
        for (int s2=0;s2<4;++s2)
            #pragma unroll
            for (int k=0;k<4;++k){ vv[s2][k]=3.4e38f; xx[s2][k]=0; }

        for (int c=0; c<32; ++c){
            const int G = q*32 + c;
            if (tid==0 && G+3 < NCHUNKS){
                const int s3 = (G+3)&3;
                mbar_wait(EMPTYB(s3), pe[s3]); pe[s3]^=1;
                MBAR_EXPECT_TX(FULLB(s3), CHUNK_B);
                bulkcp(sb+SO_B+(uint32_t)s3*CHUNK_B,
                       g_bimg + (size_t)(G+3)*CHUNK_B, CHUNK_B, FULLB(s3));
            }
            const int s = G&3;
            mbar_wait(FULLB(s), pf[s]); pf[s]^=1;

            float acc[2][4][4];
            #pragma unroll
            for (int ti=0;ti<2;++ti)
                #pragma unroll
                for (int t=0;t<4;++t)
                    #pragma unroll
                    for (int i=0;i<4;++i) acc[ti][t][i]=0.f;

            const uint32_t bbase = bRow + (uint32_t)s*CHUNK_B;

            #pragma unroll
            for (int kt=0; kt<16; ++kt){
                uint32_t bg0[4], bg1[4];
                const uint32_t cbyte = ((((uint32_t)(kt*2+suu)) ^ xorv) << 4);
                ldsm4(bg0, bbase + cbyte);
                ldsm4(bg1, bbase + 8192u + cbyte);
                mma16816(acc[0][0], &af[kt][0], bg0[0], bg0[1]);
                mma16816(acc[0][1], &af[kt][0], bg0[2], bg0[3]);
                mma16816(acc[0][2], &af[kt][0], bg1[0], bg1[1]);
                mma16816(acc[0][3], &af[kt][0], bg1[2], bg1[3]);
                mma16816(acc[1][0], &af[kt][4], bg0[0], bg0[1]);
                mma16816(acc[1][1], &af[kt][4], bg0[2], bg0[3]);
                mma16816(acc[1][2], &af[kt][4], bg1[0], bg1[1]);
                mma16816(acc[1][3], &af[kt][4], bg1[2], bg1[3]);
            }
            if (l==0) MBAR_ARRIVE(EMPTYB(s));

            #pragma unroll
            for (int ti=0;ti<2;++ti){
                #pragma unroll
                for (int t=0;t<4;++t){
                    int n = c*32 + t*8 + (l&3)*2;
                    float d0 = cbsq_s[n]   - 2.f*acc[ti][t][0];
                    float d1 = cbsq_s[n+1] - 2.f*acc[ti][t][1];
                    float d2 = cbsq_s[n]   - 2.f*acc[ti][t][2];
                    float d3 = cbsq_s[n+1] - 2.f*acc[ti][t][3];
                    INS4(vv[ti*2],   xx[ti*2],   d0, n); INS4(vv[ti*2],   xx[ti*2],   d1, n+1);
                    INS4(vv[ti*2+1], xx[ti*2+1], d2, n); INS4(vv[ti*2+1], xx[ti*2+1], d3, n+1);
                }
            }
        }

        #pragma unroll
        for (int slot=0; slot<4; ++slot){
            float* sv = vv[slot]; int* sx = xx[slot];
            float b1v = sv[0], b2v = sv[1];
            int   b1i = sx[0];
            #pragma unroll
            for (int off=1; off<=2; off<<=1){
                float o1v = __shfl_xor_sync(0xFFFFFFFFu, b1v, off);
                int   o1i = __shfl_xor_sync(0xFFFFFFFFu, b1i, off);
                float o2v = __shfl_xor_sync(0xFFFFFFFFu, b2v, off);
                if (o1v < b1v || (o1v == b1v && o1i < b1i)){
                    b2v = fminf(b1v, o2v); b1v = o1v; b1i = o1i;
                } else b2v = fminf(b2v, o1v);
            }
            int m = w*32 + (slot>>1)*16 + (l>>2) + (slot&1)*8;
            float E = CE * sqrtf(fmaxf(rsq[m], 0.f));
            float epsw = 2.1f*E + 0.02f;
            float W = b1v + epsw;
            bool flag = (b2v <= W);
            int fi = -1;
            if (flag && (l&3)==0) fi = atomicAdd(fcnt, 1);
            fi = __shfl_sync(0xFFFFFFFFu, fi, grpLead);
            int escb = (sv[3] <= W) ? 1 : 0;
            escb |= __shfl_xor_sync(0xFFFFFFFFu, escb, 1);
            escb |= __shfl_xor_sync(0xFFFFFFFFu, escb, 2);
            if (flag){
                if ((l&3)==0){ ftok[fi] = m; fesc[fi] = escb; }
                #pragma unroll
                for (int k=0;k<3;++k)
                    cand[fi*12 + (l&3)*3 + k] = (sv[k] <= W) ? sx[k] : -1;
            } else if ((l&3)==0){
                sidx[m] = b1i;
                out[QOFF + ((size_t)(q*BB+b))*TT + t0 + m] = (float)b1i;
                rsq[m] = fmaxf(rsq[m] + b1v + epsw, 0.f);
            }
        }
        __syncthreads();

        {
            const int nf = fcnt[0];
            for (int f = w; f < nf; f += 8){
                int m = ftok[f], esc = fesc[f];
                float rv[8];
                const float* rr = gres + (size_t)m*DIM + l*8;
                float4 r4a = *(const float4*)(rr), r4b = *(const float4*)(rr+4);
                rv[0]=r4a.x; rv[1]=r4a.y; rv[2]=r4a.z; rv[3]=r4a.w;
                rv[4]=r4b.x; rv[5]=r4b.y; rv[6]=r4b.z; rv[7]=r4b.w;
                float be = 3.4e38f; int bj = 0;
                if (!esc){
                    for (int k=0; k<12; ++k){
                        int j = cand[f*12+k];
                        if (j < 0) continue;
                        const float4* cr = (const float4*)(cbq + (size_t)j*DIM + l*8);
                        float4 ca = cr[0], cb2 = cr[1];
                        float s = rv[0]*ca.x + rv[1]*ca.y + rv[2]*ca.z + rv[3]*ca.w
                                + rv[4]*cb2.x + rv[5]*cb2.y + rv[6]*cb2.z + rv[7]*cb2.w;
                        #pragma unroll
                        for (int off2=16; off2>0; off2>>=1) s += __shfl_xor_sync(0xFFFFFFFFu, s, off2);
                        float e2 = cbsq_s[j] - 2.f*s;
                        if (e2 < be || (e2 == be && j < bj)){ be = e2; bj = j; }
                    }
                } else {
                    for (int j=0; j<BINS; ++j){
                        const float4* cr = (const float4*)(cbq + (size_t)j*DIM + l*8);
                        float4 ca = cr[0], cb2 = cr[1];
                        float s = rv[0]*ca.x + rv[1]*ca.y + rv[2]*ca.z + rv[3]*ca.w
                                + rv[4]*cb2.x + rv[5]*cb2.y + rv[6]*cb2.z + rv[7]*cb2.w;
                        #pragma unroll
                        for (int off2=16; off2>0; off2>>=1) s += __shfl_xor_sync(0xFFFFFFFFu, s, off2);
                        float e2 = cbsq_s[j] - 2.f*s;
                        if (e2 < be){ be = e2; bj = j; }
                    }
                }
                if (l==0){
                    sidx[m] = bj;
                    out[QOFF + ((size_t)(q*BB+b))*TT + t0 + m] = (float)bj;
                    rsq[m] = fmaxf(rsq[m] + be + 0.05f, 0.f);
                }
            }
        }
        __syncthreads();

        {
            float ssq = 0.f;
            #pragma unroll 4
            for (int m=0; m<MT; ++m){
                int ix = sidx[m];
                float cv = __ldg(cbq + (size_t)ix*DIM + tid);
                float r = gres[(size_t)m*DIM + tid];
                float rn = r - cv;
                gres[(size_t)m*DIM + tid] = rn;
                pH[m*ASTR_H + tid] = __float2half_rn(rn);
                ssq = fmaf(rn, rn, ssq);
            }
            #pragma unroll
            for (int o2=16;o2>0;o2>>=1) ssq += __shfl_xor_sync(0xFFFFFFFFu, ssq, o2);
            if (l==0) ssqs[w] = ssq;
            __syncthreads();
            if (tid==0){
                float sacc=0.f;
                #pragma unroll
                for (int ww=0; ww<8; ++ww) sacc += ssqs[ww];
                g_ssq[q*NBLK+bid] = sacc;
            }
            __syncthreads();
        }
    }

    for (int i=tid; i<DIM*MT; i+=256){
        int d = i>>8, m = i&255;
        out[((size_t)b*DIM+d)*TT + t0 + m] =
            xblk[(size_t)d*TT+m] - gres[(size_t)m*DIM + d];
    }
}

__global__ void rvq_finalize_kernel(const int* __restrict__ sr_raw, float* __restrict__ out){
    __shared__ float red[8];
    const int tid = threadIdx.x;
    float s = 0.f;
    #pragma unroll
    for (int i=0; i<NQ*NBLK/256; ++i) s += g_ssq[tid + i*256];
    #pragma unroll
    for (int o=16;o>0;o>>=1) s += __shfl_xor_sync(0xFFFFFFFFu, s, o);
    if ((tid&31)==0) red[tid>>5] = s;
    __syncthreads();
    if (tid==0){
        float tot=0.f;
        #pragma unroll
        for (int w=0; w<8; ++w) tot += red[w];
        int iv = sr_raw[0];
        float sr = (iv > 0 && iv < 100000000) ? (float)iv : __int_as_float(iv);
        out[COFF+0] = (float)NQ * 10.0f * (sr / 1000.0f);
        out[COFF+1] = tot * (0.25f / ((float)((size_t)NTOK*DIM))) / (float)NQ;
    }
}

extern "C" void kernel_launch(void* const* d_in, const int* in_sizes, int n_in,
                              void* d_out, int out_size){
    const float* x   = (const float*)d_in[0];
    const int*   sr  = (const int*)d_in[1];
    const float* cbs = (const float*)d_in[2];
    float* out = (float*)d_out;
    cudaFuncSetAttribute(rvq_main_kernel, cudaFuncAttributeMaxDynamicSharedMemorySize, SMEM_BYTES);
    rvq_prep_kernel<<<(NQ*BINS*DIM+255)/256, 256>>>(cbs);
    rvq_cbsq_kernel<<<(NQ*BINS+255)/256, 256>>>(cbs);
    rvq_main_kernel<<<NBLK, 256, SMEM_BYTES>>>(x, cbs, out);
    rvq_finalize_kernel<<<1, 256>>>(sr, out);
}

// round 17
// speedup vs baseline: 2.8492x; 1.2417x over previous
#include <cuda_runtime.h>
#include <cuda_fp16.h>
#include <cstdint>

#define NQ 8
#define BINS 1024
#define DIM 256
#define BB 8
#define TT 8192
#define NTOK (BB*TT)            // 65536
#define MT 256
#define NBLK (NTOK/MT)          // 256
#define QOFF 16777216
#define COFF (QOFF + NQ*NTOK)

#define ASTR_H 264
#define ASTR_B 528
#define A_BYTES (MT*ASTR_B)     // 135168
#define CHUNK_B 16384
#define NCHUNKS 256

#define SO_CBSQ 0
#define SO_SIDX 4096
#define SO_SSQ  5120
#define SO_MBAR 5152
#define SO_RSQ  5216
#define SO_FCNT 6240
#define SO_FTOK 6256
#define SO_FESC 7280
#define SO_CAND 8304            // 256 x 16 ints = 16384
#define SO_AHI  24704
#define SO_B    (SO_AHI + A_BYTES)      // 159872
#define SMEM_BYTES (SO_B + 4*CHUNK_B)   // 225408

__device__ __align__(128) unsigned char g_bimg[(size_t)NCHUNKS*CHUNK_B]; // 4MB
__device__ float g_res[(size_t)NTOK*DIM];   // exact fp32 residual
__device__ float g_cbsq[NQ*BINS];
__device__ int   g_cmaxbits[NQ];
__device__ float g_ssq[NQ*NBLK];

static __device__ __forceinline__ uint32_t smem_u32(const void* p){
    uint32_t a;
    asm("{ .reg .u64 t; cvta.to.shared.u64 t, %1; cvt.u32.u64 %0, t; }":"=r"(a):"l"(p));
    return a;
}
#define MBAR_INIT(a,c) asm volatile("mbarrier.init.shared.b64 [%0], %1;"::"r"(a),"r"(c):"memory")
#define MBAR_ARRIVE(a) asm volatile("mbarrier.arrive.shared.b64 _, [%0];"::"r"(a):"memory")
#define MBAR_EXPECT_TX(a,b) asm volatile("mbarrier.arrive.expect_tx.shared.b64 _, [%0], %1;"::"r"(a),"r"(b):"memory")
static __device__ __forceinline__ void mbar_wait(uint32_t a, uint32_t ph){
    asm volatile("{\n\t.reg .pred P;\nW%=: mbarrier.try_wait.parity.acquire.cta.shared::cta.b64 P, [%0], %1, 0x989680;\n\t@!P bra W%=;\n\t}"
        ::"r"(a),"r"(ph):"memory");
}
static __device__ __forceinline__ void bulkcp(uint32_t dst, const void* src,
                                              uint32_t bytes, uint32_t mb){
    asm volatile("cp.async.bulk.shared::cta.global.mbarrier::complete_tx::bytes [%0], [%1], %2, [%3];"
        ::"r"(dst),"l"(src),"r"(bytes),"r"(mb):"memory");
}
static __device__ __forceinline__ void ldsm4(uint32_t* r, uint32_t a){
    asm volatile("ldmatrix.sync.aligned.m8n8.x4.shared.b16 {%0,%1,%2,%3}, [%4];"
        :"=r"(r[0]),"=r"(r[1]),"=r"(r[2]),"=r"(r[3]):"r"(a));
}
static __device__ __forceinline__ void mma16816(float* c, const uint32_t* a,
                                                uint32_t b0, uint32_t b1){
    asm volatile("mma.sync.aligned.m16n8k16.row.col.f32.f16.f16.f32 "
        "{%0,%1,%2,%3}, {%4,%5,%6,%7}, {%8,%9}, {%0,%1,%2,%3};"
        : "+f"(c[0]),"+f"(c[1]),"+f"(c[2]),"+f"(c[3])
        : "r"(a[0]),"r"(a[1]),"r"(a[2]),"r"(a[3]),"r"(b0),"r"(b1));
}
// pack bin index into 10 mantissa LSBs (unique, branchless-orderable keys)
static __device__ __forceinline__ float packkey(float d, uint32_t n){
    return __uint_as_float((__float_as_uint(d) & 0xFFFFFC00u) | n);
}
// branchless sorted top-4 insert: 7 FMNMX
static __device__ __forceinline__ void ins4k(float* k, float v){
    float t1 = fmaxf(k[0], v);  k[0] = fminf(k[0], v);
    float t2 = fmaxf(k[1], t1); k[1] = fminf(k[1], t1);
    float t3 = fmaxf(k[2], t2); k[2] = fminf(k[2], t2);
    k[3] = fminf(k[3], t3);
}

__global__ void rvq_prep_kernel(const float* __restrict__ cbs){
    int id = blockIdx.x*blockDim.x + threadIdx.x;
    if (id >= NQ*BINS*DIM) return;
    int d = id & 255, j = (id>>8) & 1023, q = id>>18;
    __half hi = __float2half_rn(cbs[id]);
    int jc = j>>5, jr = j&31;
    uint32_t unit = (uint32_t)(d>>3);
    uint32_t off = (uint32_t)jr*512u + ((unit ^ (uint32_t)(jr&7))<<4) + (uint32_t)(d&7)*2u;
    *(__half*)(g_bimg + (size_t)(q*32+jc)*CHUNK_B + off) = hi;
}

__global__ void rvq_cbsq_kernel(const float* __restrict__ cbs){
    int id = blockIdx.x*blockDim.x + threadIdx.x;
    if (id >= NQ*BINS) return;
    const float* c = cbs + (size_t)id*DIM;
    float s0=0,s1=0,s2=0,s3=0;
    #pragma unroll 8
    for (int d=0; d<DIM; d+=4){
        float4 v = *(const float4*)(c+d);
        s0=fmaf(v.x,v.x,s0); s1=fmaf(v.y,v.y,s1); s2=fmaf(v.z,v.z,s2); s3=fmaf(v.w,v.w,s3);
    }
    float n2 = (s0+s1)+(s2+s3);
    g_cbsq[id] = n2;
    atomicMax(&g_cmaxbits[id>>10], __float_as_int(n2));
}

__global__ __launch_bounds__(256,1)
void rvq_main_kernel(const float* __restrict__ x, const float* __restrict__ cbs,
                     float* __restrict__ out){
    extern __shared__ char smc[];
    const uint32_t sb = smem_u32(smc);
    const int tid = threadIdx.x, l = tid&31, w = tid>>5, bid = blockIdx.x;
    const int b = bid>>5, t0 = (bid&31)<<8;
    const float* xblk = x + ((size_t)b*DIM)*TT + t0;
    float* gres = g_res + ((size_t)bid)*MT*DIM;
    float* cbsq_s = (float*)(smc+SO_CBSQ);
    int*   sidx   = (int*)(smc+SO_SIDX);
    float* ssqs   = (float*)(smc+SO_SSQ);
    float* rsq    = (float*)(smc+SO_RSQ);
    int*   fcnt   = (int*)(smc+SO_FCNT);
    int*   ftok   = (int*)(smc+SO_FTOK);
    int*   fesc   = (int*)(smc+SO_FESC);
    int*   cand   = (int*)(smc+SO_CAND);
    __half* pH = (__half*)(smc+SO_AHI);
    #define FULLB(i)  (sb+SO_MBAR + (uint32_t)(i)*8u)
    #define EMPTYB(i) (sb+SO_MBAR + 32u + (uint32_t)(i)*8u)

    if (tid==0){
        #pragma unroll
        for (int i=0;i<4;++i){ MBAR_INIT(FULLB(i),1); MBAR_INIT(EMPTYB(i),8); }
    }

    for (int i=tid; i<DIM*MT; i+=256){
        int d = i>>8, m = i&255;
        float v = xblk[(size_t)d*TT+m];
        pH[m*ASTR_H + d] = __float2half_rn(v);
        gres[(size_t)m*DIM + d] = v;
    }
    __syncthreads();
    if (tid < MT){
        float s = 0.f;
        const float* rr = gres + (size_t)tid*DIM;
        for (int d=0; d<DIM; d+=4){
            float4 v = *(const float4*)(rr+d);
            s = fmaf(v.x,v.x,fmaf(v.y,v.y,fmaf(v.z,v.z,fmaf(v.w,v.w,s))));
        }
        rsq[tid] = s;
    }
    __syncthreads();

    const uint32_t aW0 = sb + SO_AHI + (w*32 + (l&15))*ASTR_B + (l>>4)*16;
    const uint32_t aW1 = aW0 + 16*ASTR_B;
    const int nr  = (l&7) | ((l&16)>>1);
    const int suu = (l>>3)&1;
    const uint32_t xorv = (uint32_t)(nr&7);
    const uint32_t bRow = sb + SO_B + (uint32_t)nr*512u;
    const int grpLead = l & ~3;

    int pf[4] = {0,0,0,0};
    int pe[4] = {1,1,1,1};

    if (tid==0){
        #pragma unroll
        for (int p=0; p<3; ++p){
            mbar_wait(EMPTYB(p), pe[p]); pe[p]^=1;
            MBAR_EXPECT_TX(FULLB(p), CHUNK_B);
            bulkcp(sb+SO_B+(uint32_t)p*CHUNK_B, g_bimg + (size_t)p*CHUNK_B, CHUNK_B, FULLB(p));
        }
    }

    for (int q=0; q<NQ; ++q){
        const float* cbq = cbs + (size_t)q*BINS*DIM;
        for (int i=tid; i<BINS; i+=256) cbsq_s[i] = g_cbsq[q*BINS+i];
        if (tid==0) fcnt[0] = 0;
        const float CE = 1.96e-3f * sqrtf(__int_as_float(g_cmaxbits[q]));
        __syncthreads();

        // lane-local sorted top-4 key lists per token slot
        float kk[4][4];
        #pragma unroll
        for (int s2=0;s2<4;++s2)
            #pragma unroll
            for (int k=0;k<4;++k) kk[s2][k]=3.4e38f;

        for (int c=0; c<32; ++c){
            const int G = q*32 + c;
            if (tid==0 && G+3 < NCHUNKS){
                const int s3 = (G+3)&3;
                mbar_wait(EMPTYB(s3), pe[s3]); pe[s3]^=1;
                MBAR_EXPECT_TX(FULLB(s3), CHUNK_B);
                bulkcp(sb+SO_B+(uint32_t)s3*CHUNK_B,
                       g_bimg + (size_t)(G+3)*CHUNK_B, CHUNK_B, FULLB(s3));
            }
            const int s = G&3;
            mbar_wait(FULLB(s), pf[s]); pf[s]^=1;

            float acc[2][4][4];
            #pragma unroll
            for (int ti=0;ti<2;++ti)
                #pragma unroll
                for (int t=0;t<4;++t)
                    #pragma unroll
                    for (int i=0;i<4;++i) acc[ti][t][i]=0.f;

            const uint32_t bbase = bRow + (uint32_t)s*CHUNK_B;

            uint32_t a0[4], a1[4], bg0[4], bg1[4];
            {
                ldsm4(a0, aW0);
                ldsm4(a1, aW1);
                const uint32_t cb0 = ((((uint32_t)suu) ^ xorv) << 4);
                ldsm4(bg0, bbase + cb0);
                ldsm4(bg1, bbase + 8192u + cb0);
            }
            #pragma unroll
            for (int kt=0; kt<16; ++kt){
                uint32_t na0[4], na1[4], nb0[4], nb1[4];
                if (kt < 15){
                    ldsm4(na0, aW0 + (kt+1)*32);
                    ldsm4(na1, aW1 + (kt+1)*32);
                    const uint32_t cbn = ((((uint32_t)((kt+1)*2+suu)) ^ xorv) << 4);
                    ldsm4(nb0, bbase + cbn);
                    ldsm4(nb1, bbase + 8192u + cbn);
                }
                mma16816(acc[0][0], a0, bg0[0], bg0[1]);
                mma16816(acc[0][1], a0, bg0[2], bg0[3]);
                mma16816(acc[0][2], a0, bg1[0], bg1[1]);
                mma16816(acc[0][3], a0, bg1[2], bg1[3]);
                mma16816(acc[1][0], a1, bg0[0], bg0[1]);
                mma16816(acc[1][1], a1, bg0[2], bg0[3]);
                mma16816(acc[1][2], a1, bg1[0], bg1[1]);
                mma16816(acc[1][3], a1, bg1[2], bg1[3]);
                if (kt < 15){
                    #pragma unroll
                    for (int i=0;i<4;++i){
                        a0[i]=na0[i]; a1[i]=na1[i]; bg0[i]=nb0[i]; bg1[i]=nb1[i];
                    }
                }
            }
            if (l==0) MBAR_ARRIVE(EMPTYB(s));

            // branchless packed-key top-4 epilogue
            #pragma unroll
            for (int ti=0;ti<2;++ti){
                #pragma unroll
                for (int t=0;t<4;++t){
                    uint32_t n = (uint32_t)(c*32 + t*8 + (l&3)*2);
                    float cq0 = cbsq_s[n], cq1 = cbsq_s[n+1];
                    ins4k(kk[ti*2],   packkey(fmaf(-2.f, acc[ti][t][0], cq0), n));
                    ins4k(kk[ti*2],   packkey(fmaf(-2.f, acc[ti][t][1], cq1), n+1));
                    ins4k(kk[ti*2+1], packkey(fmaf(-2.f, acc[ti][t][2], cq0), n));
                    ins4k(kk[ti*2+1], packkey(fmaf(-2.f, acc[ti][t][3], cq1), n+1));
                }
            }
        }

        #pragma unroll
        for (int slot=0; slot<4; ++slot){
            float* pk = kk[slot];                 // lane-local sorted top-4
            float g1 = pk[0], g2 = pk[1];
            #pragma unroll
            for (int off=1; off<=2; off<<=1){
                float o1 = __shfl_xor_sync(0xFFFFFFFFu, g1, off);
                float o2 = __shfl_xor_sync(0xFFFFFFFFu, g2, off);
                float mx = fmaxf(g1, o1);
                g1 = fminf(g1, o1);
                g2 = fminf(fminf(g2, o2), mx);
            }
            int m = w*32 + (slot>>1)*16 + (l>>2) + (slot&1)*8;
            float E = CE * sqrtf(fmaxf(rsq[m], 0.f));
            float epsw = 2.1f*E + 0.03f + 6e-4f*(fabsf(g1)+1.f);
            float W = g1 + epsw;
            bool flag = (g2 <= W);
            int fi = -1;
            if (flag && (l&3)==0) fi = atomicAdd(fcnt, 1);
            fi = __shfl_sync(0xFFFFFFFFu, fi, grpLead);
            int escb = (pk[3] <= W) ? 1 : 0;      // same strength as R14: lane 4th-best
            escb |= __shfl_xor_sync(0xFFFFFFFFu, escb, 1);
            escb |= __shfl_xor_sync(0xFFFFFFFFu, escb, 2);
            if (flag){
                if ((l&3)==0){ ftok[fi] = m; fesc[fi] = escb; }
                #pragma unroll
                for (int k=0;k<4;++k)
                    cand[fi*16 + (l&3)*4 + k] =
                        (pk[k] <= W) ? (int)(__float_as_uint(pk[k])&1023u) : -1;
            } else if ((l&3)==0){
                int b1i = (int)(__float_as_uint(g1)&1023u);
                sidx[m] = b1i;
                out[QOFF + ((size_t)(q*BB+b))*TT + t0 + m] = (float)b1i;
                rsq[m] = fmaxf(rsq[m] + g1 + epsw, 0.f);
            }
        }
        __syncthreads();

        {
            const int nf = fcnt[0];
            for (int f = w; f < nf; f += 8){
                int m = ftok[f], esc = fesc[f];
                float rv[8];
                const float* rr = gres + (size_t)m*DIM + l*8;
                float4 r4a = *(const float4*)(rr), r4b = *(const float4*)(rr+4);
                rv[0]=r4a.x; rv[1]=r4a.y; rv[2]=r4a.z; rv[3]=r4a.w;
                rv[4]=r4b.x; rv[5]=r4b.y; rv[6]=r4b.z; rv[7]=r4b.w;
                float be = 3.4e38f; int bj = 0;
                if (!esc){
                    for (int k=0; k<16; ++k){
                        int j = cand[f*16+k];
                        if (j < 0) continue;
                        const float4* cr = (const float4*)(cbq + (size_t)j*DIM + l*8);
                        float4 ca = cr[0], cb2 = cr[1];
                        float s = rv[0]*ca.x + rv[1]*ca.y + rv[2]*ca.z + rv[3]*ca.w
                                + rv[4]*cb2.x + rv[5]*cb2.y + rv[6]*cb2.z + rv[7]*cb2.w;
                        #pragma unroll
                        for (int off2=16; off2>0; off2>>=1) s += __shfl_xor_sync(0xFFFFFFFFu, s, off2);
                        float e2 = cbsq_s[j] - 2.f*s;
                        if (e2 < be || (e2 == be && j < bj)){ be = e2; bj = j; }
                    }
                } else {
                    for (int j=0; j<BINS; ++j){
                        const float4* cr = (const float4*)(cbq + (size_t)j*DIM + l*8);
                        float4 ca = cr[0], cb2 = cr[1];
                        float s = rv[0]*ca.x + rv[1]*ca.y + rv[2]*ca.z + rv[3]*ca.w
                                + rv[4]*cb2.x + rv[5]*cb2.y + rv[6]*cb2.z + rv[7]*cb2.w;
                        #pragma unroll
                        for (int off2=16; off2>0; off2>>=1) s += __shfl_xor_sync(0xFFFFFFFFu, s, off2);
                        float e2 = cbsq_s[j] - 2.f*s;
                        if (e2 < be){ be = e2; bj = j; }
                    }
                }
                if (l==0){
                    sidx[m] = bj;
                    out[QOFF + ((size_t)(q*BB+b))*TT + t0 + m] = (float)bj;
                    rsq[m] = fmaxf(rsq[m] + be + 0.05f, 0.f);
                }
            }
        }
        __syncthreads();

        {
            float ssq = 0.f;
            #pragma unroll 4
            for (int m=0; m<MT; ++m){
                int ix = sidx[m];
                float cv = __ldg(cbq + (size_t)ix*DIM + tid);
                float r = gres[(size_t)m*DIM + tid];
                float rn = r - cv;
                gres[(size_t)m*DIM + tid] = rn;
                pH[m*ASTR_H + tid] = __float2half_rn(rn);
                ssq = fmaf(rn, rn, ssq);
            }
            #pragma unroll
            for (int o2=16;o2>0;o2>>=1) ssq += __shfl_xor_sync(0xFFFFFFFFu, ssq, o2);
            if (l==0) ssqs[w] = ssq;
            __syncthreads();
            if (tid==0){
                float sacc=0.f;
                #pragma unroll
                for (int ww=0; ww<8; ++ww) sacc += ssqs[ww];
                g_ssq[q*NBLK+bid] = sacc;
            }
            __syncthreads();
        }
    }

    for (int i=tid; i<DIM*MT; i+=256){
        int d = i>>8, m = i&255;
        out[((size_t)b*DIM+d)*TT + t0 + m] =
            xblk[(size_t)d*TT+m] - gres[(size_t)m*DIM + d];
    }
}

__global__ void rvq_finalize_kernel(const int* __restrict__ sr_raw, float* __restrict__ out){
    __shared__ float red[8];
    const int tid = threadIdx.x;
    float s = 0.f;
    #pragma unroll
    for (int i=0; i<NQ*NBLK/256; ++i) s += g_ssq[tid + i*256];
    #pragma unroll
    for (int o=16;o>0;o>>=1) s += __shfl_xor_sync(0xFFFFFFFFu, s, o);
    if ((tid&31)==0) red[tid>>5] = s;
    __syncthreads();
    if (tid==0){
        float tot=0.f;
        #pragma unroll
        for (int w=0; w<8; ++w) tot += red[w];
        int iv = sr_raw[0];
        float sr = (iv > 0 && iv < 100000000) ? (float)iv : __int_as_float(iv);
        out[COFF+0] = (float)NQ * 10.0f * (sr / 1000.0f);
        out[COFF+1] = tot * (0.25f / ((float)((size_t)NTOK*DIM))) / (float)NQ;
    }
}

extern "C" void kernel_launch(void* const* d_in, const int* in_sizes, int n_in,
                              void* d_out, int out_size){
    const float* x   = (const float*)d_in[0];
    const int*   sr  = (const int*)d_in[1];
    const float* cbs = (const float*)d_in[2];
    float* out = (float*)d_out;
    cudaFuncSetAttribute(rvq_main_kernel, cudaFuncAttributeMaxDynamicSharedMemorySize, SMEM_BYTES);
    rvq_prep_kernel<<<(NQ*BINS*DIM+255)/256, 256>>>(cbs);
    rvq_cbsq_kernel<<<(NQ*BINS+255)/256, 256>>>(cbs);
    rvq_main_kernel<<<NBLK, 256, SMEM_BYTES>>>(x, cbs, out);
    rvq_finalize_kernel<<<1, 256>>>(sr, out);
}